// round 1
// baseline (speedup 1.0000x reference)
#include <cuda_runtime.h>

// Problem constants
#define BSZ 8
#define SEQT 256
#define NJ 24
#define DIM 512
#define NH 8
#define HD 64

#define QKV_ELEMS (BSZ * NJ * SEQT * DIM)  // 25,165,824

// Scratch (layout [b][j][t][e], e = h*HD + d)
__device__ float g_Q[QKV_ELEMS];
__device__ float g_K[QKV_ELEMS];
__device__ float g_V[QKV_ELEMS];
__device__ float g_O[QKV_ELEMS];

// ---------------------------------------------------------------------------
// Kernel 1: fused per-joint Q/K/V projection.
// q/k/v[b,t,j,e] = sum_d x[b,t,j,d] * W{q,k,v}[j,d,e]
// GEMM per joint: A = x rows (m = b*T+t, 2048 rows, row stride NJ*DIM),
//                 B = W[j] (K-major, row d contiguous in e).
// Tile: BM=128, BN=64, BK=16; 256 threads; each thread 8x4 outputs x3 matrices.
// ---------------------------------------------------------------------------
#define K1_BM 128
#define K1_BN 64
#define K1_BK 16

__global__ __launch_bounds__(256)
void qkv_proj_kernel(const float* __restrict__ x,
                     const float* __restrict__ Wq,
                     const float* __restrict__ Wk,
                     const float* __restrict__ Wv)
{
    __shared__ __align__(16) float As[K1_BK * K1_BM];      // As[k][m]
    __shared__ __align__(16) float Bs[3][K1_BK * K1_BN];   // Bs[p][k][n]

    const int nt = blockIdx.x;   // 0..7
    const int mt = blockIdx.y;   // 0..15
    const int j  = blockIdx.z;   // 0..23
    const int tid = threadIdx.x;
    const int tx = tid & 15;     // n-group
    const int ty = tid >> 4;     // m-group

    const float* Wp[3] = { Wq, Wk, Wv };

    float acc[3][8][4];
#pragma unroll
    for (int p = 0; p < 3; p++)
#pragma unroll
        for (int i = 0; i < 8; i++)
#pragma unroll
            for (int jj = 0; jj < 4; jj++)
                acc[p][i][jj] = 0.0f;

    const int woff0 = j * DIM * DIM + nt * K1_BN;

    for (int k0 = 0; k0 < DIM; k0 += K1_BK) {
        // Load A tile 128x16 (store transposed As[k][m])
#pragma unroll
        for (int l = 0; l < 2; l++) {
            int idx = tid + l * 256;
            int row = idx >> 2;
            int kv  = idx & 3;
            const float4 v = *(const float4*)(x +
                (((mt * K1_BM + row) * NJ + j) * DIM + k0 + kv * 4));
            As[(kv * 4 + 0) * K1_BM + row] = v.x;
            As[(kv * 4 + 1) * K1_BM + row] = v.y;
            As[(kv * 4 + 2) * K1_BM + row] = v.z;
            As[(kv * 4 + 3) * K1_BM + row] = v.w;
        }
        // Load 3 B tiles 16x64
        {
            int kr = tid >> 4;
            int nv = tid & 15;
            int goff = woff0 + (k0 + kr) * DIM + nv * 4;
#pragma unroll
            for (int p = 0; p < 3; p++)
                *(float4*)&Bs[p][kr * K1_BN + nv * 4] =
                    *(const float4*)(Wp[p] + goff);
        }
        __syncthreads();

#pragma unroll
        for (int kk = 0; kk < K1_BK; kk++) {
            float4 a0 = *(const float4*)&As[kk * K1_BM + ty * 8];
            float4 a1 = *(const float4*)&As[kk * K1_BM + ty * 8 + 4];
            float a[8] = { a0.x, a0.y, a0.z, a0.w, a1.x, a1.y, a1.z, a1.w };
#pragma unroll
            for (int p = 0; p < 3; p++) {
                float4 bv = *(const float4*)&Bs[p][kk * K1_BN + tx * 4];
                float bb[4] = { bv.x, bv.y, bv.z, bv.w };
#pragma unroll
                for (int i = 0; i < 8; i++)
#pragma unroll
                    for (int jj = 0; jj < 4; jj++)
                        acc[p][i][jj] += a[i] * bb[jj];
            }
        }
        __syncthreads();
    }

    // Epilogue: store to [b][j][t][e]
#pragma unroll
    for (int i = 0; i < 8; i++) {
        int m = mt * K1_BM + ty * 8 + i;
        int b = m >> 8;
        int t = m & (SEQT - 1);
        int base = ((b * NJ + j) * SEQT + t) * DIM + nt * K1_BN + tx * 4;
        *(float4*)&g_Q[base] = make_float4(acc[0][i][0], acc[0][i][1], acc[0][i][2], acc[0][i][3]);
        *(float4*)&g_K[base] = make_float4(acc[1][i][0], acc[1][i][1], acc[1][i][2], acc[1][i][3]);
        *(float4*)&g_V[base] = make_float4(acc[2][i][0], acc[2][i][1], acc[2][i][2], acc[2][i][3]);
    }
}

// ---------------------------------------------------------------------------
// Kernel 2: attention. One block per (b,j,h). K and V resident in 128 KB
// dynamic smem; thread t handles query row t with online softmax, q/o in regs.
// ---------------------------------------------------------------------------
__global__ __launch_bounds__(256)
void attn_kernel()
{
    extern __shared__ float sm[];
    float* Ks = sm;                 // [T][HD]
    float* Vs = sm + SEQT * HD;     // [T][HD]

    const int bjh = blockIdx.x;     // bj*8 + h
    const int h  = bjh & (NH - 1);
    const int bj = bjh >> 3;        // b*NJ + j
    const int tid = threadIdx.x;    // query index t

    const float* kb = g_K + (size_t)bj * SEQT * DIM + h * HD;
    const float* vb = g_V + (size_t)bj * SEQT * DIM + h * HD;

    // cooperative smem fill (coalesced: consecutive threads cover contiguous d)
    for (int idx = tid; idx < SEQT * HD / 4; idx += 256) {
        int s  = idx >> 4;
        int dv = (idx & 15) * 4;
        *(float4*)&Ks[s * HD + dv] = *(const float4*)(kb + s * DIM + dv);
        *(float4*)&Vs[s * HD + dv] = *(const float4*)(vb + s * DIM + dv);
    }

    // q row into registers, pre-scaled by hd^-0.5 = 0.125
    float q[HD];
    {
        const float* qb = g_Q + ((size_t)bj * SEQT + tid) * DIM + h * HD;
#pragma unroll
        for (int dv = 0; dv < HD; dv += 4) {
            float4 v = *(const float4*)(qb + dv);
            q[dv + 0] = v.x * 0.125f;
            q[dv + 1] = v.y * 0.125f;
            q[dv + 2] = v.z * 0.125f;
            q[dv + 3] = v.w * 0.125f;
        }
    }
    __syncthreads();

    float m = -1e30f, l = 0.0f;
    float o[HD];
#pragma unroll
    for (int d = 0; d < HD; d++) o[d] = 0.0f;

    for (int s = 0; s < SEQT; s++) {
        float dot = 0.0f;
#pragma unroll
        for (int dv = 0; dv < HD; dv += 4) {
            float4 kv = *(const float4*)&Ks[s * HD + dv];
            dot += q[dv + 0] * kv.x + q[dv + 1] * kv.y
                 + q[dv + 2] * kv.z + q[dv + 3] * kv.w;
        }
        float nm = fmaxf(m, dot);
        float sc = __expf(m - nm);
        float p  = __expf(dot - nm);
        l = l * sc + p;
#pragma unroll
        for (int dv = 0; dv < HD; dv += 4) {
            float4 vv = *(const float4*)&Vs[s * HD + dv];
            o[dv + 0] = o[dv + 0] * sc + p * vv.x;
            o[dv + 1] = o[dv + 1] * sc + p * vv.y;
            o[dv + 2] = o[dv + 2] * sc + p * vv.z;
            o[dv + 3] = o[dv + 3] * sc + p * vv.w;
        }
        m = nm;
    }

    const float inv = 1.0f / l;
    float* ob = g_O + ((size_t)bj * SEQT + tid) * DIM + h * HD;
#pragma unroll
    for (int dv = 0; dv < HD; dv += 4) {
        *(float4*)(ob + dv) = make_float4(o[dv + 0] * inv, o[dv + 1] * inv,
                                          o[dv + 2] * inv, o[dv + 3] * inv);
    }
}

// ---------------------------------------------------------------------------
// Kernel 3: output projection. y[r][e] = sum_d g_O[r][d] * Wo[e][d] + bo[e]
// g_O rows r = (b*NJ+j)*T + t are contiguous. Output goes to [b][t][j][e].
// Tile: BM=BN=128, BK=16; 256 threads; 8x8 per thread.
// ---------------------------------------------------------------------------
#define K3_BM 128
#define K3_BN 128
#define K3_BK 16

__global__ __launch_bounds__(256)
void out_proj_kernel(const float* __restrict__ Wo,
                     const float* __restrict__ bo,
                     float* __restrict__ out)
{
    __shared__ __align__(16) float As[K3_BK * K3_BM];   // As[k][m]
    __shared__ __align__(16) float Bs[K3_BK * K3_BN];   // Bs[k][n] (= Wo[n][k])

    const int nt = blockIdx.x;   // 0..3
    const int mt = blockIdx.y;   // 0..383
    const int tid = threadIdx.x;
    const int tx = tid & 15;
    const int ty = tid >> 4;

    float acc[8][8];
#pragma unroll
    for (int i = 0; i < 8; i++)
#pragma unroll
        for (int jj = 0; jj < 8; jj++)
            acc[i][jj] = 0.0f;

    for (int k0 = 0; k0 < DIM; k0 += K3_BK) {
        // A tile 128x16 from g_O (rows contiguous), stored transposed
#pragma unroll
        for (int l = 0; l < 2; l++) {
            int idx = tid + l * 256;
            int row = idx >> 2;
            int kv  = idx & 3;
            const float4 v = *(const float4*)(g_O +
                ((size_t)(mt * K3_BM + row)) * DIM + k0 + kv * 4);
            As[(kv * 4 + 0) * K3_BM + row] = v.x;
            As[(kv * 4 + 1) * K3_BM + row] = v.y;
            As[(kv * 4 + 2) * K3_BM + row] = v.z;
            As[(kv * 4 + 3) * K3_BM + row] = v.w;
        }
        // B tile: Wo[e][d] read along contiguous d, scattered to Bs[d][e]
#pragma unroll
        for (int l = 0; l < 2; l++) {
            int idx = tid + l * 256;
            int e  = idx >> 2;
            int dv = idx & 3;
            const float4 v = *(const float4*)(Wo +
                (nt * K3_BN + e) * DIM + k0 + dv * 4);
            Bs[(dv * 4 + 0) * K3_BN + e] = v.x;
            Bs[(dv * 4 + 1) * K3_BN + e] = v.y;
            Bs[(dv * 4 + 2) * K3_BN + e] = v.z;
            Bs[(dv * 4 + 3) * K3_BN + e] = v.w;
        }
        __syncthreads();

#pragma unroll
        for (int kk = 0; kk < K3_BK; kk++) {
            float4 a0 = *(const float4*)&As[kk * K3_BM + ty * 8];
            float4 a1 = *(const float4*)&As[kk * K3_BM + ty * 8 + 4];
            float4 b0 = *(const float4*)&Bs[kk * K3_BN + tx * 8];
            float4 b1 = *(const float4*)&Bs[kk * K3_BN + tx * 8 + 4];
            float a[8] = { a0.x, a0.y, a0.z, a0.w, a1.x, a1.y, a1.z, a1.w };
            float b[8] = { b0.x, b0.y, b0.z, b0.w, b1.x, b1.y, b1.z, b1.w };
#pragma unroll
            for (int i = 0; i < 8; i++)
#pragma unroll
                for (int jj = 0; jj < 8; jj++)
                    acc[i][jj] += a[i] * b[jj];
        }
        __syncthreads();
    }

    // bias
    float bias[8];
    {
        float4 v0 = *(const float4*)(bo + nt * K3_BN + tx * 8);
        float4 v1 = *(const float4*)(bo + nt * K3_BN + tx * 8 + 4);
        bias[0] = v0.x; bias[1] = v0.y; bias[2] = v0.z; bias[3] = v0.w;
        bias[4] = v1.x; bias[5] = v1.y; bias[6] = v1.z; bias[7] = v1.w;
    }

#pragma unroll
    for (int i = 0; i < 8; i++) {
        int r = mt * K3_BM + ty * 8 + i;          // (b*NJ + j)*T + t
        int b = r / (NJ * SEQT);
        int rem = r - b * (NJ * SEQT);
        int j = rem >> 8;
        int t = rem & (SEQT - 1);
        int obase = ((b * SEQT + t) * NJ + j) * DIM + nt * K3_BN + tx * 8;
        *(float4*)(out + obase) = make_float4(acc[i][0] + bias[0], acc[i][1] + bias[1],
                                              acc[i][2] + bias[2], acc[i][3] + bias[3]);
        *(float4*)(out + obase + 4) = make_float4(acc[i][4] + bias[4], acc[i][5] + bias[5],
                                                  acc[i][6] + bias[6], acc[i][7] + bias[7]);
    }
}

// ---------------------------------------------------------------------------
extern "C" void kernel_launch(void* const* d_in, const int* in_sizes, int n_in,
                              void* d_out, int out_size)
{
    const float* x  = (const float*)d_in[0];
    const float* Wq = (const float*)d_in[1];
    const float* Wk = (const float*)d_in[2];
    const float* Wv = (const float*)d_in[3];
    const float* Wo = (const float*)d_in[4];
    const float* bo = (const float*)d_in[5];
    float* out = (float*)d_out;

    // 1) fused QKV projection
    dim3 g1(DIM / K1_BN, (BSZ * SEQT) / K1_BM, NJ);   // (8, 16, 24)
    qkv_proj_kernel<<<g1, 256>>>(x, Wq, Wk, Wv);

    // 2) attention
    const int attn_smem = 2 * SEQT * HD * (int)sizeof(float);  // 131072 B
    cudaFuncSetAttribute(attn_kernel,
                         cudaFuncAttributeMaxDynamicSharedMemorySize, attn_smem);
    attn_kernel<<<BSZ * NJ * NH, 256, attn_smem>>>();

    // 3) output projection + bias
    dim3 g3(DIM / K3_BN, (BSZ * SEQT * NJ) / K3_BM);  // (4, 384)
    out_proj_kernel<<<g3, 256>>>(Wo, bo, out);
}

// round 3
// speedup vs baseline: 1.5882x; 1.5882x over previous
#include <cuda_runtime.h>
#include <cstdint>

// Problem constants
#define BSZ 8
#define SEQT 256
#define NJ 24
#define DIM 512
#define NH 8
#define HD 64

#define QKV_ELEMS (BSZ * NJ * SEQT * DIM)  // 25,165,824

// Scratch (layout [b][j][t][e], e = h*HD + d)
__device__ float g_Q[QKV_ELEMS];
__device__ float g_K[QKV_ELEMS];
__device__ float g_V[QKV_ELEMS];
__device__ float g_O[QKV_ELEMS];

__device__ __forceinline__ float to_tf32(float x) {
    uint32_t r;
    asm("cvt.rna.tf32.f32 %0, %1;" : "=r"(r) : "f"(x));
    return __uint_as_float(r);
}

__device__ __forceinline__ void mma_tf32(
    float& c0, float& c1, float& c2, float& c3,
    uint32_t a0, uint32_t a1, uint32_t a2, uint32_t a3,
    uint32_t b0, uint32_t b1)
{
    asm volatile(
        "mma.sync.aligned.m16n8k8.row.col.f32.tf32.tf32.f32 "
        "{%0,%1,%2,%3}, {%4,%5,%6,%7}, {%8,%9}, {%0,%1,%2,%3};\n"
        : "+f"(c0), "+f"(c1), "+f"(c2), "+f"(c3)
        : "r"(a0), "r"(a1), "r"(a2), "r"(a3), "r"(b0), "r"(b1));
}

// Smem strides: 36 floats -> frag LDS conflict-free ((4g+q) mod 32 distinct)
#define SA 36
#define SB 36

// ---------------------------------------------------------------------------
// Kernel 1: per-joint Q/K/V projection on tensor cores (tf32).
// grid: (N/64=8, M/128=16, 3*24=72); block 256 (8 warps, 4x2 of 32x32 tiles).
// C[m][e] = sum_d x[b,t,j,d] * W[j][d][e]
// ---------------------------------------------------------------------------
__global__ __launch_bounds__(256)
void qkv_tc_kernel(const float* __restrict__ x,
                   const float* __restrict__ Wq,
                   const float* __restrict__ Wk,
                   const float* __restrict__ Wv)
{
    __shared__ __align__(16) float As[128 * SA];
    __shared__ __align__(16) float Bs[64 * SB];

    const int nt = blockIdx.x;
    const int mt = blockIdx.y;
    const int z  = blockIdx.z;
    const int j  = z % NJ;
    const int p  = z / NJ;

    const float* W   = (p == 0) ? Wq : ((p == 1) ? Wk : Wv);
    float* outp      = (p == 0) ? g_Q : ((p == 1) ? g_K : g_V);

    const int tid  = threadIdx.x;
    const int wid  = tid >> 5;
    const int lane = tid & 31;
    const int wm   = (wid >> 1) * 32;   // warp M offset in block tile
    const int wn   = (wid & 1) * 32;    // warp N offset
    const int grp  = lane >> 2;         // 0..7
    const int qd   = lane & 3;          // 0..3

    float acc[2][4][4];
#pragma unroll
    for (int i = 0; i < 2; i++)
#pragma unroll
        for (int jn = 0; jn < 4; jn++)
#pragma unroll
            for (int c = 0; c < 4; c++)
                acc[i][jn][c] = 0.0f;

    const uint32_t* Asu = (const uint32_t*)As;
    const uint32_t* Bsu = (const uint32_t*)Bs;

    const size_t wbase = (size_t)j * DIM * DIM + nt * 64;

    for (int k0 = 0; k0 < DIM; k0 += 32) {
        // Stage A: 128x32 from x = 1024 float4s -> 4 iterations of 256 threads
#pragma unroll
        for (int l = 0; l < 4; l++) {
            int idx = tid + l * 256;
            int row = idx >> 3;
            int kv  = idx & 7;
            int m   = mt * 128 + row;
            float4 v = *(const float4*)(x + ((size_t)m * NJ + j) * DIM + k0 + kv * 4);
            float* d = &As[row * SA + kv * 4];
            d[0] = to_tf32(v.x); d[1] = to_tf32(v.y);
            d[2] = to_tf32(v.z); d[3] = to_tf32(v.w);
        }
        // Stage B (transpose): W[k][n] -> Bs[n][k]  (32x64 = 512 float4s)
#pragma unroll
        for (int l = 0; l < 2; l++) {
            int idx = tid + l * 256;
            int kr  = idx >> 4;       // 0..31
            int nv  = idx & 15;       // 0..15 (float4 along n)
            float4 v = *(const float4*)(W + wbase + (size_t)(k0 + kr) * DIM + nv * 4);
            Bs[(nv * 4 + 0) * SB + kr] = to_tf32(v.x);
            Bs[(nv * 4 + 1) * SB + kr] = to_tf32(v.y);
            Bs[(nv * 4 + 2) * SB + kr] = to_tf32(v.z);
            Bs[(nv * 4 + 3) * SB + kr] = to_tf32(v.w);
        }
        __syncthreads();

#pragma unroll
        for (int kk = 0; kk < 4; kk++) {
            const int k = kk * 8;
            uint32_t a[2][4];
#pragma unroll
            for (int i = 0; i < 2; i++) {
                int r0 = wm + 16 * i + grp;
                a[i][0] = Asu[r0 * SA + k + qd];
                a[i][1] = Asu[(r0 + 8) * SA + k + qd];
                a[i][2] = Asu[r0 * SA + k + qd + 4];
                a[i][3] = Asu[(r0 + 8) * SA + k + qd + 4];
            }
            uint32_t b[4][2];
#pragma unroll
            for (int jn = 0; jn < 4; jn++) {
                int n = wn + 8 * jn + grp;
                b[jn][0] = Bsu[n * SB + k + qd];
                b[jn][1] = Bsu[n * SB + k + qd + 4];
            }
#pragma unroll
            for (int i = 0; i < 2; i++)
#pragma unroll
                for (int jn = 0; jn < 4; jn++)
                    mma_tf32(acc[i][jn][0], acc[i][jn][1], acc[i][jn][2], acc[i][jn][3],
                             a[i][0], a[i][1], a[i][2], a[i][3],
                             b[jn][0], b[jn][1]);
        }
        __syncthreads();
    }

    // Epilogue: store to [b][j][t][e]
#pragma unroll
    for (int i = 0; i < 2; i++) {
        int m = mt * 128 + wm + 16 * i + grp;
        int b = m >> 8;
        int t = m & (SEQT - 1);
        size_t base0 = (((size_t)(b * NJ + j) * SEQT) + t) * DIM + nt * 64 + wn;
        size_t base1 = base0 + (size_t)8 * DIM;   // row m+8 (same b,j)
#pragma unroll
        for (int jn = 0; jn < 4; jn++) {
            int col = 8 * jn + 2 * qd;
            *(float2*)&outp[base0 + col] = make_float2(acc[i][jn][0], acc[i][jn][1]);
            *(float2*)&outp[base1 + col] = make_float2(acc[i][jn][2], acc[i][jn][3]);
        }
    }
}

// ---------------------------------------------------------------------------
// Kernel 2: attention. One block per (b,j,h); K,V in 128KB dynamic smem.
// Online softmax with rare-rescale branch (1 exp on common path).
// ---------------------------------------------------------------------------
__global__ __launch_bounds__(256)
void attn_kernel()
{
    extern __shared__ float sm[];
    float* Ks = sm;                 // [T][HD]
    float* Vs = sm + SEQT * HD;     // [T][HD]

    const int bjh = blockIdx.x;
    const int h  = bjh & (NH - 1);
    const int bj = bjh >> 3;
    const int tid = threadIdx.x;    // query index t

    const float* kb = g_K + (size_t)bj * SEQT * DIM + h * HD;
    const float* vb = g_V + (size_t)bj * SEQT * DIM + h * HD;

    for (int idx = tid; idx < SEQT * HD / 4; idx += 256) {
        int s  = idx >> 4;
        int dv = (idx & 15) * 4;
        *(float4*)&Ks[s * HD + dv] = *(const float4*)(kb + s * DIM + dv);
        *(float4*)&Vs[s * HD + dv] = *(const float4*)(vb + s * DIM + dv);
    }

    float q[HD];
    {
        const float* qb = g_Q + ((size_t)bj * SEQT + tid) * DIM + h * HD;
#pragma unroll
        for (int dv = 0; dv < HD; dv += 4) {
            float4 v = *(const float4*)(qb + dv);
            q[dv + 0] = v.x * 0.125f;
            q[dv + 1] = v.y * 0.125f;
            q[dv + 2] = v.z * 0.125f;
            q[dv + 3] = v.w * 0.125f;
        }
    }
    __syncthreads();

    float m = -1e30f, l = 0.0f;
    float o[HD];
#pragma unroll
    for (int d = 0; d < HD; d++) o[d] = 0.0f;

    for (int s = 0; s < SEQT; s++) {
        float dot = 0.0f;
#pragma unroll
        for (int dv = 0; dv < HD; dv += 4) {
            float4 kv = *(const float4*)&Ks[s * HD + dv];
            dot += q[dv + 0] * kv.x + q[dv + 1] * kv.y
                 + q[dv + 2] * kv.z + q[dv + 3] * kv.w;
        }
        if (dot <= m) {
            // common path: no rescale, one exp
            float p = __expf(dot - m);
            l += p;
#pragma unroll
            for (int dv = 0; dv < HD; dv += 4) {
                float4 vv = *(const float4*)&Vs[s * HD + dv];
                o[dv + 0] += p * vv.x;
                o[dv + 1] += p * vv.y;
                o[dv + 2] += p * vv.z;
                o[dv + 3] += p * vv.w;
            }
        } else {
            // rescale path (rare: ~ln(T) times per thread)
            float sc = __expf(m - dot);
            m = dot;
            l = l * sc + 1.0f;
#pragma unroll
            for (int dv = 0; dv < HD; dv += 4) {
                float4 vv = *(const float4*)&Vs[s * HD + dv];
                o[dv + 0] = o[dv + 0] * sc + vv.x;
                o[dv + 1] = o[dv + 1] * sc + vv.y;
                o[dv + 2] = o[dv + 2] * sc + vv.z;
                o[dv + 3] = o[dv + 3] * sc + vv.w;
            }
        }
    }

    const float inv = 1.0f / l;
    float* ob = g_O + ((size_t)bj * SEQT + tid) * DIM + h * HD;
#pragma unroll
    for (int dv = 0; dv < HD; dv += 4) {
        *(float4*)(ob + dv) = make_float4(o[dv + 0] * inv, o[dv + 1] * inv,
                                          o[dv + 2] * inv, o[dv + 3] * inv);
    }
}

// ---------------------------------------------------------------------------
// Kernel 3: output projection on tensor cores (tf32) + bias.
// y[r][e] = sum_d g_O[r][d] * Wo[e][d] + bo[e]
// grid: (8, 384); block 256.
// ---------------------------------------------------------------------------
__global__ __launch_bounds__(256)
void proj_tc_kernel(const float* __restrict__ Wo,
                    const float* __restrict__ bo,
                    float* __restrict__ out)
{
    __shared__ __align__(16) float As[128 * SA];
    __shared__ __align__(16) float Bs[64 * SB];

    const int nt = blockIdx.x;
    const int mt = blockIdx.y;

    const int tid  = threadIdx.x;
    const int wid  = tid >> 5;
    const int lane = tid & 31;
    const int wm   = (wid >> 1) * 32;
    const int wn   = (wid & 1) * 32;
    const int grp  = lane >> 2;
    const int qd   = lane & 3;

    float acc[2][4][4];
#pragma unroll
    for (int i = 0; i < 2; i++)
#pragma unroll
        for (int jn = 0; jn < 4; jn++)
#pragma unroll
            for (int c = 0; c < 4; c++)
                acc[i][jn][c] = 0.0f;

    const uint32_t* Asu = (const uint32_t*)As;
    const uint32_t* Bsu = (const uint32_t*)Bs;

    for (int k0 = 0; k0 < DIM; k0 += 32) {
        // Stage A from g_O: 128x32 = 1024 float4s -> 4 iterations
#pragma unroll
        for (int l = 0; l < 4; l++) {
            int idx = tid + l * 256;
            int row = idx >> 3;
            int kv  = idx & 7;
            float4 v = *(const float4*)(g_O + ((size_t)(mt * 128 + row)) * DIM + k0 + kv * 4);
            float* d = &As[row * SA + kv * 4];
            d[0] = to_tf32(v.x); d[1] = to_tf32(v.y);
            d[2] = to_tf32(v.z); d[3] = to_tf32(v.w);
        }
        // Stage B: Wo[e][d] already [n][k] row-major (64x32 = 512 float4s)
#pragma unroll
        for (int l = 0; l < 2; l++) {
            int idx = tid + l * 256;
            int n   = idx >> 3;
            int kv  = idx & 7;
            float4 v = *(const float4*)(Wo + (size_t)(nt * 64 + n) * DIM + k0 + kv * 4);
            float* d = &Bs[n * SB + kv * 4];
            d[0] = to_tf32(v.x); d[1] = to_tf32(v.y);
            d[2] = to_tf32(v.z); d[3] = to_tf32(v.w);
        }
        __syncthreads();

#pragma unroll
        for (int kk = 0; kk < 4; kk++) {
            const int k = kk * 8;
            uint32_t a[2][4];
#pragma unroll
            for (int i = 0; i < 2; i++) {
                int r0 = wm + 16 * i + grp;
                a[i][0] = Asu[r0 * SA + k + qd];
                a[i][1] = Asu[(r0 + 8) * SA + k + qd];
                a[i][2] = Asu[r0 * SA + k + qd + 4];
                a[i][3] = Asu[(r0 + 8) * SA + k + qd + 4];
            }
            uint32_t b[4][2];
#pragma unroll
            for (int jn = 0; jn < 4; jn++) {
                int n = wn + 8 * jn + grp;
                b[jn][0] = Bsu[n * SB + k + qd];
                b[jn][1] = Bsu[n * SB + k + qd + 4];
            }
#pragma unroll
            for (int i = 0; i < 2; i++)
#pragma unroll
                for (int jn = 0; jn < 4; jn++)
                    mma_tf32(acc[i][jn][0], acc[i][jn][1], acc[i][jn][2], acc[i][jn][3],
                             a[i][0], a[i][1], a[i][2], a[i][3],
                             b[jn][0], b[jn][1]);
        }
        __syncthreads();
    }

    // Epilogue with bias, remap r=(b*NJ+j)*T+t -> [b][t][j][e]
#pragma unroll
    for (int i = 0; i < 2; i++) {
        int r = mt * 128 + wm + 16 * i + grp;
        int b = r / (NJ * SEQT);
        int rem = r - b * (NJ * SEQT);
        int jj = rem >> 8;
        int t  = rem & (SEQT - 1);
        size_t base0 = (((size_t)(b * SEQT + t) * NJ) + jj) * DIM + nt * 64 + wn;
        size_t base1 = base0 + (size_t)8 * NJ * DIM;  // t+8 (same b, jj)
#pragma unroll
        for (int jn = 0; jn < 4; jn++) {
            int col = 8 * jn + 2 * qd;
            float2 bb = *(const float2*)(bo + nt * 64 + wn + col);
            *(float2*)&out[base0 + col] = make_float2(acc[i][jn][0] + bb.x,
                                                      acc[i][jn][1] + bb.y);
            *(float2*)&out[base1 + col] = make_float2(acc[i][jn][2] + bb.x,
                                                      acc[i][jn][3] + bb.y);
        }
    }
}

// ---------------------------------------------------------------------------
extern "C" void kernel_launch(void* const* d_in, const int* in_sizes, int n_in,
                              void* d_out, int out_size)
{
    const float* x  = (const float*)d_in[0];
    const float* Wq = (const float*)d_in[1];
    const float* Wk = (const float*)d_in[2];
    const float* Wv = (const float*)d_in[3];
    const float* Wo = (const float*)d_in[4];
    const float* bo = (const float*)d_in[5];
    float* out = (float*)d_out;

    // 1) QKV projection (tf32 tensor cores)
    dim3 g1(DIM / 64, (BSZ * SEQT) / 128, 3 * NJ);   // (8, 16, 72)
    qkv_tc_kernel<<<g1, 256>>>(x, Wq, Wk, Wv);

    // 2) attention
    const int attn_smem = 2 * SEQT * HD * (int)sizeof(float);  // 131072 B
    cudaFuncSetAttribute(attn_kernel,
                         cudaFuncAttributeMaxDynamicSharedMemorySize, attn_smem);
    attn_kernel<<<BSZ * NJ * NH, 256, attn_smem>>>();

    // 3) output projection + bias (tf32 tensor cores)
    dim3 g3(DIM / 64, (BSZ * SEQT * NJ) / 128);      // (8, 384)
    proj_tc_kernel<<<g3, 256>>>(Wo, bo, out);
}

// round 4
// speedup vs baseline: 1.9827x; 1.2484x over previous
#include <cuda_runtime.h>
#include <cstdint>

// Problem constants
#define BSZ 8
#define SEQT 256
#define NJ 24
#define DIM 512
#define NH 8
#define HD 64

#define QKV_ELEMS (BSZ * NJ * SEQT * DIM)  // 25,165,824

// Scratch (layout [b][j][t][e], e = h*HD + d)
__device__ float g_Q[QKV_ELEMS];
__device__ float g_K[QKV_ELEMS];
__device__ float g_V[QKV_ELEMS];
__device__ float g_O[QKV_ELEMS];

typedef unsigned long long u64;

__device__ __forceinline__ float to_tf32(float x) {
    uint32_t r;
    asm("cvt.rna.tf32.f32 %0, %1;" : "=r"(r) : "f"(x));
    return __uint_as_float(r);
}

__device__ __forceinline__ void mma_tf32(
    float& c0, float& c1, float& c2, float& c3,
    uint32_t a0, uint32_t a1, uint32_t a2, uint32_t a3,
    uint32_t b0, uint32_t b1)
{
    asm volatile(
        "mma.sync.aligned.m16n8k8.row.col.f32.tf32.tf32.f32 "
        "{%0,%1,%2,%3}, {%4,%5,%6,%7}, {%8,%9}, {%0,%1,%2,%3};\n"
        : "+f"(c0), "+f"(c1), "+f"(c2), "+f"(c3)
        : "r"(a0), "r"(a1), "r"(a2), "r"(a3), "r"(b0), "r"(b1));
}

// packed f32x2 helpers (Blackwell FFMA2 pipe)
__device__ __forceinline__ u64 fma2(u64 a, u64 b, u64 c) {
    u64 d;
    asm("fma.rn.f32x2 %0, %1, %2, %3;" : "=l"(d) : "l"(a), "l"(b), "l"(c));
    return d;
}
__device__ __forceinline__ u64 mul2(u64 a, u64 b) {
    u64 d;
    asm("mul.rn.f32x2 %0, %1, %2;" : "=l"(d) : "l"(a), "l"(b));
    return d;
}
__device__ __forceinline__ u64 pack2(float x, float y) {
    u64 r;
    asm("mov.b64 %0, {%1, %2};" : "=l"(r) : "f"(x), "f"(y));
    return r;
}
__device__ __forceinline__ void unpack2(u64 a, float& x, float& y) {
    asm("mov.b64 {%0, %1}, %2;" : "=f"(x), "=f"(y) : "l"(a));
}

// Smem stride 36: frag LDS bank = (4*grp + qd + c) mod 32 -> conflict-free
#define SA 36
#define SB 36
#define BUF_FLOATS (128 * SA + 128 * SB)   // one buffer: A(128x32) + B(128x32)
#define GEMM_SMEM (2 * BUF_FLOATS * 4)     // 73728 bytes

// ---------------------------------------------------------------------------
// Kernel 1: per-joint Q/K/V projection, tf32 tensor cores.
// Block tile 128x128, BK=32, 256 threads = 8 warps (2M x 4N), warp 64x32.
// Double-buffered smem, register-prefetch pipeline.
// grid: (4, 16, 72)
// ---------------------------------------------------------------------------
__global__ __launch_bounds__(256)
void qkv_tc_kernel(const float* __restrict__ x,
                   const float* __restrict__ Wq,
                   const float* __restrict__ Wk,
                   const float* __restrict__ Wv)
{
    extern __shared__ float smem[];

    const int nt = blockIdx.x;   // 0..3  (N/128)
    const int mt = blockIdx.y;   // 0..15 (M/128)
    const int z  = blockIdx.z;
    const int j  = z % NJ;
    const int p  = z / NJ;

    const float* W = (p == 0) ? Wq : ((p == 1) ? Wk : Wv);
    float* outp    = (p == 0) ? g_Q : ((p == 1) ? g_K : g_V);

    const int tid  = threadIdx.x;
    const int wid  = tid >> 5;
    const int lane = tid & 31;
    const int wm   = (wid >> 2) * 64;   // 0 or 64
    const int wn   = (wid & 3) * 32;    // 0..96
    const int grp  = lane >> 2;
    const int qd   = lane & 3;

    // staging task coords
    const int arow = tid >> 3;          // A: row 0..31 step... (idx>>3 with idx=tid+l*256)
    const int akv  = tid & 7;
    const int bn   = tid & 127;         // B: column n
    const int bkh  = tid >> 7;          // 0/1

    const size_t wbase = (size_t)j * DIM * DIM + nt * 128;

    float acc[4][4][4];
#pragma unroll
    for (int i = 0; i < 4; i++)
#pragma unroll
        for (int jn = 0; jn < 4; jn++)
#pragma unroll
            for (int c = 0; c < 4; c++)
                acc[i][jn][c] = 0.0f;

    float pa[16];   // A prefetch: 4 float4
    float pb[16];   // B prefetch: 4 columns x 4 k

    // --- load k-block into registers ---
    auto loadA = [&](int k0) {
#pragma unroll
        for (int l = 0; l < 4; l++) {
            int row = arow + l * 32;
            float4 v = *(const float4*)(x +
                ((size_t)(mt * 128 + row) * NJ + j) * DIM + k0 + akv * 4);
            pa[l * 4 + 0] = v.x; pa[l * 4 + 1] = v.y;
            pa[l * 4 + 2] = v.z; pa[l * 4 + 3] = v.w;
        }
#pragma unroll
        for (int l = 0; l < 4; l++) {
            int kq = 2 * l + bkh;       // k-quad 0..7
#pragma unroll
            for (int e = 0; e < 4; e++)
                pb[l * 4 + e] = W[wbase + (size_t)(k0 + kq * 4 + e) * DIM + bn];
        }
    };
    auto storeS = [&](float* Ab, float* Bb) {
#pragma unroll
        for (int l = 0; l < 4; l++) {
            int row = arow + l * 32;
            float* d = &Ab[row * SA + akv * 4];
            d[0] = to_tf32(pa[l * 4 + 0]); d[1] = to_tf32(pa[l * 4 + 1]);
            d[2] = to_tf32(pa[l * 4 + 2]); d[3] = to_tf32(pa[l * 4 + 3]);
        }
#pragma unroll
        for (int l = 0; l < 4; l++) {
            int kq = 2 * l + bkh;
            float* d = &Bb[bn * SB + kq * 4];   // STS.128, 8-lane phases cover 32 banks
            d[0] = to_tf32(pb[l * 4 + 0]); d[1] = to_tf32(pb[l * 4 + 1]);
            d[2] = to_tf32(pb[l * 4 + 2]); d[3] = to_tf32(pb[l * 4 + 3]);
        }
    };

    loadA(0);
    storeS(smem, smem + 128 * SA);
    __syncthreads();

    int buf = 0;
    for (int kb = 0; kb < DIM / 32; kb++) {
        if (kb + 1 < DIM / 32) loadA((kb + 1) * 32);   // LDG in flight under MMAs

        const float* Ab = smem + buf * BUF_FLOATS;
        const float* Bb = Ab + 128 * SA;
        const uint32_t* Asu = (const uint32_t*)Ab;
        const uint32_t* Bsu = (const uint32_t*)Bb;

#pragma unroll
        for (int kk = 0; kk < 4; kk++) {
            const int k = kk * 8;
            uint32_t a[4][4];
#pragma unroll
            for (int i = 0; i < 4; i++) {
                int r0 = wm + 16 * i + grp;
                a[i][0] = Asu[r0 * SA + k + qd];
                a[i][1] = Asu[(r0 + 8) * SA + k + qd];
                a[i][2] = Asu[r0 * SA + k + qd + 4];
                a[i][3] = Asu[(r0 + 8) * SA + k + qd + 4];
            }
            uint32_t b[4][2];
#pragma unroll
            for (int jn = 0; jn < 4; jn++) {
                int n = wn + 8 * jn + grp;
                b[jn][0] = Bsu[n * SB + k + qd];
                b[jn][1] = Bsu[n * SB + k + qd + 4];
            }
#pragma unroll
            for (int i = 0; i < 4; i++)
#pragma unroll
                for (int jn = 0; jn < 4; jn++)
                    mma_tf32(acc[i][jn][0], acc[i][jn][1], acc[i][jn][2], acc[i][jn][3],
                             a[i][0], a[i][1], a[i][2], a[i][3],
                             b[jn][0], b[jn][1]);
        }

        if (kb + 1 < DIM / 32) {
            float* Ab2 = smem + (buf ^ 1) * BUF_FLOATS;
            storeS(Ab2, Ab2 + 128 * SA);
        }
        __syncthreads();
        buf ^= 1;
    }

    // Epilogue: store to [b][j][t][e]
#pragma unroll
    for (int i = 0; i < 4; i++) {
        int m = mt * 128 + wm + 16 * i + grp;
        int b = m >> 8;
        int t = m & (SEQT - 1);
        size_t base0 = (((size_t)(b * NJ + j) * SEQT) + t) * DIM + nt * 128 + wn;
        size_t base1 = base0 + (size_t)8 * DIM;   // row m+8 (same b,j; never crosses)
#pragma unroll
        for (int jn = 0; jn < 4; jn++) {
            int col = 8 * jn + 2 * qd;
            *(float2*)&outp[base0 + col] = make_float2(acc[i][jn][0], acc[i][jn][1]);
            *(float2*)&outp[base1 + col] = make_float2(acc[i][jn][2], acc[i][jn][3]);
        }
    }
}

// ---------------------------------------------------------------------------
// Kernel 2: attention, packed f32x2 FMA. One block per (b,j,h).
// K,V in 128KB smem; thread t = one query row, online softmax (rare rescale).
// ---------------------------------------------------------------------------
__global__ __launch_bounds__(256)
void attn_kernel()
{
    extern __shared__ float sm[];
    float* Ks = sm;                 // [T][HD]
    float* Vs = sm + SEQT * HD;     // [T][HD]

    const int bjh = blockIdx.x;
    const int h  = bjh & (NH - 1);
    const int bj = bjh >> 3;
    const int tid = threadIdx.x;    // query index t

    const float* kb = g_K + (size_t)bj * SEQT * DIM + h * HD;
    const float* vb = g_V + (size_t)bj * SEQT * DIM + h * HD;

    for (int idx = tid; idx < SEQT * HD / 4; idx += 256) {
        int s  = idx >> 4;
        int dv = (idx & 15) * 4;
        *(float4*)&Ks[s * HD + dv] = *(const float4*)(kb + s * DIM + dv);
        *(float4*)&Vs[s * HD + dv] = *(const float4*)(vb + s * DIM + dv);
    }

    // q packed (pre-scaled by hd^-0.5), o packed
    u64 q2[HD / 2], o2[HD / 2];
    {
        const ulonglong2* qb = (const ulonglong2*)(g_Q + ((size_t)bj * SEQT + tid) * DIM + h * HD);
        const u64 s2 = pack2(0.125f, 0.125f);
#pragma unroll
        for (int i = 0; i < HD / 4; i++) {
            ulonglong2 w = qb[i];
            q2[2 * i + 0] = mul2(w.x, s2);
            q2[2 * i + 1] = mul2(w.y, s2);
        }
    }
#pragma unroll
    for (int i = 0; i < HD / 2; i++) o2[i] = 0ULL;
    __syncthreads();

    float m = -1e30f, l = 0.0f;

    for (int s = 0; s < SEQT; s++) {
        const ulonglong2* k2 = (const ulonglong2*)&Ks[s * HD];
        u64 d2[4] = {0ULL, 0ULL, 0ULL, 0ULL};
#pragma unroll
        for (int i = 0; i < HD / 4; i++) {
            ulonglong2 w = k2[i];
            d2[(2 * i + 0) & 3] = fma2(q2[2 * i + 0], w.x, d2[(2 * i + 0) & 3]);
            d2[(2 * i + 1) & 3] = fma2(q2[2 * i + 1], w.y, d2[(2 * i + 1) & 3]);
        }
        float dot;
        {
            float x0, y0, x1, y1, x2, y2, x3, y3;
            unpack2(d2[0], x0, y0); unpack2(d2[1], x1, y1);
            unpack2(d2[2], x2, y2); unpack2(d2[3], x3, y3);
            dot = ((x0 + y0) + (x1 + y1)) + ((x2 + y2) + (x3 + y3));
        }

        const ulonglong2* v2 = (const ulonglong2*)&Vs[s * HD];
        if (dot <= m) {
            // common path: one exp, no rescale
            float pr = __expf(dot - m);
            l += pr;
            u64 p2 = pack2(pr, pr);
#pragma unroll
            for (int i = 0; i < HD / 4; i++) {
                ulonglong2 w = v2[i];
                o2[2 * i + 0] = fma2(p2, w.x, o2[2 * i + 0]);
                o2[2 * i + 1] = fma2(p2, w.y, o2[2 * i + 1]);
            }
        } else {
            // rescale path (rare): p = 1
            float sc = __expf(m - dot);
            m = dot;
            l = l * sc + 1.0f;
            u64 sc2 = pack2(sc, sc);
#pragma unroll
            for (int i = 0; i < HD / 4; i++) {
                ulonglong2 w = v2[i];
                o2[2 * i + 0] = fma2(o2[2 * i + 0], sc2, w.x);
                o2[2 * i + 1] = fma2(o2[2 * i + 1], sc2, w.y);
            }
        }
    }

    const float inv = 1.0f / l;
    float* ob = g_O + ((size_t)bj * SEQT + tid) * DIM + h * HD;
#pragma unroll
    for (int i = 0; i < HD / 2; i += 2) {
        float x0, y0, x1, y1;
        unpack2(o2[i], x0, y0);
        unpack2(o2[i + 1], x1, y1);
        *(float4*)(ob + 2 * i) = make_float4(x0 * inv, y0 * inv, x1 * inv, y1 * inv);
    }
}

// ---------------------------------------------------------------------------
// Kernel 3: output projection + bias, same GEMM skeleton (B needs no transpose:
// Wo is [n][k] row-major). grid: (4, 48).
// ---------------------------------------------------------------------------
__global__ __launch_bounds__(256)
void proj_tc_kernel(const float* __restrict__ Wo,
                    const float* __restrict__ bo,
                    float* __restrict__ out)
{
    extern __shared__ float smem[];

    const int nt = blockIdx.x;   // 0..3
    const int mt = blockIdx.y;   // 0..47

    const int tid  = threadIdx.x;
    const int wid  = tid >> 5;
    const int lane = tid & 31;
    const int wm   = (wid >> 2) * 64;
    const int wn   = (wid & 3) * 32;
    const int grp  = lane >> 2;
    const int qd   = lane & 3;

    const int arow = tid >> 3;
    const int akv  = tid & 7;

    float acc[4][4][4];
#pragma unroll
    for (int i = 0; i < 4; i++)
#pragma unroll
        for (int jn = 0; jn < 4; jn++)
#pragma unroll
            for (int c = 0; c < 4; c++)
                acc[i][jn][c] = 0.0f;

    float pa[16];
    float pb[16];

    auto loadA = [&](int k0) {
#pragma unroll
        for (int l = 0; l < 4; l++) {
            int row = arow + l * 32;
            float4 v = *(const float4*)(g_O +
                ((size_t)(mt * 128 + row)) * DIM + k0 + akv * 4);
            pa[l * 4 + 0] = v.x; pa[l * 4 + 1] = v.y;
            pa[l * 4 + 2] = v.z; pa[l * 4 + 3] = v.w;
        }
#pragma unroll
        for (int l = 0; l < 4; l++) {
            int n = arow + l * 32;
            float4 v = *(const float4*)(Wo +
                (size_t)(nt * 128 + n) * DIM + k0 + akv * 4);
            pb[l * 4 + 0] = v.x; pb[l * 4 + 1] = v.y;
            pb[l * 4 + 2] = v.z; pb[l * 4 + 3] = v.w;
        }
    };
    auto storeS = [&](float* Ab, float* Bb) {
#pragma unroll
        for (int l = 0; l < 4; l++) {
            int row = arow + l * 32;
            float* d = &Ab[row * SA + akv * 4];
            d[0] = to_tf32(pa[l * 4 + 0]); d[1] = to_tf32(pa[l * 4 + 1]);
            d[2] = to_tf32(pa[l * 4 + 2]); d[3] = to_tf32(pa[l * 4 + 3]);
        }
#pragma unroll
        for (int l = 0; l < 4; l++) {
            int n = arow + l * 32;
            float* d = &Bb[n * SB + akv * 4];
            d[0] = to_tf32(pb[l * 4 + 0]); d[1] = to_tf32(pb[l * 4 + 1]);
            d[2] = to_tf32(pb[l * 4 + 2]); d[3] = to_tf32(pb[l * 4 + 3]);
        }
    };

    loadA(0);
    storeS(smem, smem + 128 * SA);
    __syncthreads();

    int buf = 0;
    for (int kb = 0; kb < DIM / 32; kb++) {
        if (kb + 1 < DIM / 32) loadA((kb + 1) * 32);

        const float* Ab = smem + buf * BUF_FLOATS;
        const float* Bb = Ab + 128 * SA;
        const uint32_t* Asu = (const uint32_t*)Ab;
        const uint32_t* Bsu = (const uint32_t*)Bb;

#pragma unroll
        for (int kk = 0; kk < 4; kk++) {
            const int k = kk * 8;
            uint32_t a[4][4];
#pragma unroll
            for (int i = 0; i < 4; i++) {
                int r0 = wm + 16 * i + grp;
                a[i][0] = Asu[r0 * SA + k + qd];
                a[i][1] = Asu[(r0 + 8) * SA + k + qd];
                a[i][2] = Asu[r0 * SA + k + qd + 4];
                a[i][3] = Asu[(r0 + 8) * SA + k + qd + 4];
            }
            uint32_t b[4][2];
#pragma unroll
            for (int jn = 0; jn < 4; jn++) {
                int n = wn + 8 * jn + grp;
                b[jn][0] = Bsu[n * SB + k + qd];
                b[jn][1] = Bsu[n * SB + k + qd + 4];
            }
#pragma unroll
            for (int i = 0; i < 4; i++)
#pragma unroll
                for (int jn = 0; jn < 4; jn++)
                    mma_tf32(acc[i][jn][0], acc[i][jn][1], acc[i][jn][2], acc[i][jn][3],
                             a[i][0], a[i][1], a[i][2], a[i][3],
                             b[jn][0], b[jn][1]);
        }

        if (kb + 1 < DIM / 32) {
            float* Ab2 = smem + (buf ^ 1) * BUF_FLOATS;
            storeS(Ab2, Ab2 + 128 * SA);
        }
        __syncthreads();
        buf ^= 1;
    }

    // Epilogue with bias, remap r=(b*NJ+j)*T+t -> [b][t][j][e]
#pragma unroll
    for (int i = 0; i < 4; i++) {
        int r = mt * 128 + wm + 16 * i + grp;
        int b = r / (NJ * SEQT);
        int rem = r - b * (NJ * SEQT);
        int jj = rem >> 8;
        int t  = rem & (SEQT - 1);
        size_t base0 = (((size_t)(b * SEQT + t) * NJ) + jj) * DIM + nt * 128 + wn;
        size_t base1 = base0 + (size_t)8 * NJ * DIM;  // t+8 (same b, jj; never crosses)
#pragma unroll
        for (int jn = 0; jn < 4; jn++) {
            int col = 8 * jn + 2 * qd;
            float2 bb = *(const float2*)(bo + nt * 128 + wn + col);
            *(float2*)&out[base0 + col] = make_float2(acc[i][jn][0] + bb.x,
                                                      acc[i][jn][1] + bb.y);
            *(float2*)&out[base1 + col] = make_float2(acc[i][jn][2] + bb.x,
                                                      acc[i][jn][3] + bb.y);
        }
    }
}

// ---------------------------------------------------------------------------
extern "C" void kernel_launch(void* const* d_in, const int* in_sizes, int n_in,
                              void* d_out, int out_size)
{
    const float* x  = (const float*)d_in[0];
    const float* Wq = (const float*)d_in[1];
    const float* Wk = (const float*)d_in[2];
    const float* Wv = (const float*)d_in[3];
    const float* Wo = (const float*)d_in[4];
    const float* bo = (const float*)d_in[5];
    float* out = (float*)d_out;

    // 1) QKV projection
    cudaFuncSetAttribute(qkv_tc_kernel,
                         cudaFuncAttributeMaxDynamicSharedMemorySize, GEMM_SMEM);
    dim3 g1(DIM / 128, (BSZ * SEQT) / 128, 3 * NJ);   // (4, 16, 72)
    qkv_tc_kernel<<<g1, 256, GEMM_SMEM>>>(x, Wq, Wk, Wv);

    // 2) attention
    const int attn_smem = 2 * SEQT * HD * (int)sizeof(float);  // 131072 B
    cudaFuncSetAttribute(attn_kernel,
                         cudaFuncAttributeMaxDynamicSharedMemorySize, attn_smem);
    attn_kernel<<<BSZ * NJ * NH, 256, attn_smem>>>();

    // 3) output projection + bias
    cudaFuncSetAttribute(proj_tc_kernel,
                         cudaFuncAttributeMaxDynamicSharedMemorySize, GEMM_SMEM);
    dim3 g3(DIM / 128, (BSZ * SEQT * NJ) / 128);      // (4, 48)
    proj_tc_kernel<<<g3, 256, GEMM_SMEM>>>(Wo, bo, out);
}

// round 5
// speedup vs baseline: 3.4436x; 1.7368x over previous
#include <cuda_runtime.h>
#include <cstdint>

// Problem constants
#define BSZ 8
#define SEQT 256
#define NJ 24
#define DIM 512
#define NH 8
#define HD 64

#define QKV_ELEMS (BSZ * NJ * SEQT * DIM)  // 25,165,824

// Scratch (layout [b][j][t][e], e = h*HD + d)
__device__ float g_Q[QKV_ELEMS];
__device__ float g_K[QKV_ELEMS];
__device__ float g_V[QKV_ELEMS];
__device__ float g_O[QKV_ELEMS];

__device__ __forceinline__ float to_tf32(float x) {
    uint32_t r;
    asm("cvt.rna.tf32.f32 %0, %1;" : "=r"(r) : "f"(x));
    return __uint_as_float(r);
}
__device__ __forceinline__ uint32_t f2tf(float x) {
    uint32_t r;
    asm("cvt.rna.tf32.f32 %0, %1;" : "=r"(r) : "f"(x));
    return r;
}

__device__ __forceinline__ void mma_tf32(
    float& c0, float& c1, float& c2, float& c3,
    uint32_t a0, uint32_t a1, uint32_t a2, uint32_t a3,
    uint32_t b0, uint32_t b1)
{
    asm volatile(
        "mma.sync.aligned.m16n8k8.row.col.f32.tf32.tf32.f32 "
        "{%0,%1,%2,%3}, {%4,%5,%6,%7}, {%8,%9}, {%0,%1,%2,%3};\n"
        : "+f"(c0), "+f"(c1), "+f"(c2), "+f"(c3)
        : "r"(a0), "r"(a1), "r"(a2), "r"(a3), "r"(b0), "r"(b1));
}

// Smem stride 36: frag LDS bank = (4*grp + qd + c) mod 32 -> conflict-free
#define SA 36
#define SB 36
#define BUF_FLOATS (128 * SA + 128 * SB)   // one buffer: A(128x32) + B(128x32)
#define GEMM_SMEM (2 * BUF_FLOATS * 4)     // 73728 bytes

// ---------------------------------------------------------------------------
// Kernel 1: per-joint Q/K/V projection, tf32 tensor cores. (unchanged, passing)
// ---------------------------------------------------------------------------
__global__ __launch_bounds__(256)
void qkv_tc_kernel(const float* __restrict__ x,
                   const float* __restrict__ Wq,
                   const float* __restrict__ Wk,
                   const float* __restrict__ Wv)
{
    extern __shared__ float smem[];

    const int nt = blockIdx.x;
    const int mt = blockIdx.y;
    const int z  = blockIdx.z;
    const int j  = z % NJ;
    const int p  = z / NJ;

    const float* W = (p == 0) ? Wq : ((p == 1) ? Wk : Wv);
    float* outp    = (p == 0) ? g_Q : ((p == 1) ? g_K : g_V);

    const int tid  = threadIdx.x;
    const int wid  = tid >> 5;
    const int lane = tid & 31;
    const int wm   = (wid >> 2) * 64;
    const int wn   = (wid & 3) * 32;
    const int grp  = lane >> 2;
    const int qd   = lane & 3;

    const int arow = tid >> 3;
    const int akv  = tid & 7;
    const int bn   = tid & 127;
    const int bkh  = tid >> 7;

    const size_t wbase = (size_t)j * DIM * DIM + nt * 128;

    float acc[4][4][4];
#pragma unroll
    for (int i = 0; i < 4; i++)
#pragma unroll
        for (int jn = 0; jn < 4; jn++)
#pragma unroll
            for (int c = 0; c < 4; c++)
                acc[i][jn][c] = 0.0f;

    float pa[16];
    float pb[16];

    auto loadA = [&](int k0) {
#pragma unroll
        for (int l = 0; l < 4; l++) {
            int row = arow + l * 32;
            float4 v = *(const float4*)(x +
                ((size_t)(mt * 128 + row) * NJ + j) * DIM + k0 + akv * 4);
            pa[l * 4 + 0] = v.x; pa[l * 4 + 1] = v.y;
            pa[l * 4 + 2] = v.z; pa[l * 4 + 3] = v.w;
        }
#pragma unroll
        for (int l = 0; l < 4; l++) {
            int kq = 2 * l + bkh;
#pragma unroll
            for (int e = 0; e < 4; e++)
                pb[l * 4 + e] = W[wbase + (size_t)(k0 + kq * 4 + e) * DIM + bn];
        }
    };
    auto storeS = [&](float* Ab, float* Bb) {
#pragma unroll
        for (int l = 0; l < 4; l++) {
            int row = arow + l * 32;
            float* d = &Ab[row * SA + akv * 4];
            d[0] = to_tf32(pa[l * 4 + 0]); d[1] = to_tf32(pa[l * 4 + 1]);
            d[2] = to_tf32(pa[l * 4 + 2]); d[3] = to_tf32(pa[l * 4 + 3]);
        }
#pragma unroll
        for (int l = 0; l < 4; l++) {
            int kq = 2 * l + bkh;
            float* d = &Bb[bn * SB + kq * 4];
            d[0] = to_tf32(pb[l * 4 + 0]); d[1] = to_tf32(pb[l * 4 + 1]);
            d[2] = to_tf32(pb[l * 4 + 2]); d[3] = to_tf32(pb[l * 4 + 3]);
        }
    };

    loadA(0);
    storeS(smem, smem + 128 * SA);
    __syncthreads();

    int buf = 0;
    for (int kb = 0; kb < DIM / 32; kb++) {
        if (kb + 1 < DIM / 32) loadA((kb + 1) * 32);

        const float* Ab = smem + buf * BUF_FLOATS;
        const float* Bb = Ab + 128 * SA;
        const uint32_t* Asu = (const uint32_t*)Ab;
        const uint32_t* Bsu = (const uint32_t*)Bb;

#pragma unroll
        for (int kk = 0; kk < 4; kk++) {
            const int k = kk * 8;
            uint32_t a[4][4];
#pragma unroll
            for (int i = 0; i < 4; i++) {
                int r0 = wm + 16 * i + grp;
                a[i][0] = Asu[r0 * SA + k + qd];
                a[i][1] = Asu[(r0 + 8) * SA + k + qd];
                a[i][2] = Asu[r0 * SA + k + qd + 4];
                a[i][3] = Asu[(r0 + 8) * SA + k + qd + 4];
            }
            uint32_t b[4][2];
#pragma unroll
            for (int jn = 0; jn < 4; jn++) {
                int n = wn + 8 * jn + grp;
                b[jn][0] = Bsu[n * SB + k + qd];
                b[jn][1] = Bsu[n * SB + k + qd + 4];
            }
#pragma unroll
            for (int i = 0; i < 4; i++)
#pragma unroll
                for (int jn = 0; jn < 4; jn++)
                    mma_tf32(acc[i][jn][0], acc[i][jn][1], acc[i][jn][2], acc[i][jn][3],
                             a[i][0], a[i][1], a[i][2], a[i][3],
                             b[jn][0], b[jn][1]);
        }

        if (kb + 1 < DIM / 32) {
            float* Ab2 = smem + (buf ^ 1) * BUF_FLOATS;
            storeS(Ab2, Ab2 + 128 * SA);
        }
        __syncthreads();
        buf ^= 1;
    }

#pragma unroll
    for (int i = 0; i < 4; i++) {
        int m = mt * 128 + wm + 16 * i + grp;
        int b = m >> 8;
        int t = m & (SEQT - 1);
        size_t base0 = (((size_t)(b * NJ + j) * SEQT) + t) * DIM + nt * 128 + wn;
        size_t base1 = base0 + (size_t)8 * DIM;
#pragma unroll
        for (int jn = 0; jn < 4; jn++) {
            int col = 8 * jn + 2 * qd;
            *(float2*)&outp[base0 + col] = make_float2(acc[i][jn][0], acc[i][jn][1]);
            *(float2*)&outp[base1 + col] = make_float2(acc[i][jn][2], acc[i][jn][3]);
        }
    }
}

// ---------------------------------------------------------------------------
// Kernel 2: flash-style tensor-core attention.
// One block per (b,j,h), 512 threads = 16 warps, warp handles 16 query rows.
// Q (pre-scaled, tf32), K, V^T staged once in smem; 4 chunks of 64 keys:
// S = Q K^T (mma), branchless online softmax, P via quad-shuffle C->A frags,
// O += P V (mma). No syncthreads inside the chunk loop.
// ---------------------------------------------------------------------------
#define KS_STRIDE 68
#define VT_STRIDE 260
#define ATT_SMEM_FLOATS (2 * SEQT * KS_STRIDE + HD * VT_STRIDE)  // 51456
#define ATT_SMEM (ATT_SMEM_FLOATS * 4)                           // 205824 B

__global__ __launch_bounds__(512)
void attn_tc_kernel()
{
    extern __shared__ float sm[];
    float* Qs = sm;                              // [256][68] tf32, pre-scaled
    float* Ks = sm + SEQT * KS_STRIDE;           // [256][68] tf32
    float* Vt = sm + 2 * SEQT * KS_STRIDE;       // [64][260] tf32 (V transposed)

    const int bjh = blockIdx.x;
    const int h   = bjh & (NH - 1);
    const int bj  = bjh >> 3;
    const int tid  = threadIdx.x;
    const int wid  = tid >> 5;
    const int lane = tid & 31;
    const int grp  = lane >> 2;
    const int qd   = lane & 3;
    const int m0   = wid * 16;     // this warp's query-row base

    const size_t base = (size_t)bj * SEQT * DIM + h * HD;
    const float* qg = g_Q + base;
    const float* kg = g_K + base;
    const float* vg = g_V + base;

    // Stage Q (scaled by hd^-0.5, tf32) and K (tf32): [s][d], stride 68
#pragma unroll
    for (int l = 0; l < 8; l++) {
        int idx = tid + l * 512;            // 0..4095
        int s  = idx >> 4;
        int dq = (idx & 15) * 4;
        float4 q = *(const float4*)(qg + (size_t)s * DIM + dq);
        float* dst = &Qs[s * KS_STRIDE + dq];
        dst[0] = to_tf32(q.x * 0.125f); dst[1] = to_tf32(q.y * 0.125f);
        dst[2] = to_tf32(q.z * 0.125f); dst[3] = to_tf32(q.w * 0.125f);
        float4 k = *(const float4*)(kg + (size_t)s * DIM + dq);
        float* dk = &Ks[s * KS_STRIDE + dq];
        dk[0] = to_tf32(k.x); dk[1] = to_tf32(k.y);
        dk[2] = to_tf32(k.z); dk[3] = to_tf32(k.w);
    }
    // Stage V transposed: Vt[d][s], stride 260 (reads coalesced across lanes)
#pragma unroll
    for (int l = 0; l < 8; l++) {
        int idx = tid + l * 512;            // 0..4095
        int d  = idx & 63;
        int s0 = (idx >> 6) * 4;
        float4 v;
        v.x = to_tf32(vg[(size_t)(s0 + 0) * DIM + d]);
        v.y = to_tf32(vg[(size_t)(s0 + 1) * DIM + d]);
        v.z = to_tf32(vg[(size_t)(s0 + 2) * DIM + d]);
        v.w = to_tf32(vg[(size_t)(s0 + 3) * DIM + d]);
        *(float4*)&Vt[d * VT_STRIDE + s0] = v;
    }
    __syncthreads();

    const uint32_t* QsU = (const uint32_t*)Qs;
    const uint32_t* KsU = (const uint32_t*)Ks;
    const uint32_t* VtU = (const uint32_t*)Vt;

    float oacc[8][4];
#pragma unroll
    for (int jn = 0; jn < 8; jn++)
#pragma unroll
        for (int c = 0; c < 4; c++) oacc[jn][c] = 0.0f;
    float mrow[2] = { -1e30f, -1e30f };
    float lrow[2] = { 0.0f, 0.0f };

    const int src1 = (lane & ~3) | (qd >> 1);
    const int src2 = src1 + 2;

    for (int ch = 0; ch < 4; ch++) {
        // ---- S = Q K^T over this 64-key chunk ----
        float sacc[8][4];
#pragma unroll
        for (int jn = 0; jn < 8; jn++)
#pragma unroll
            for (int c = 0; c < 4; c++) sacc[jn][c] = 0.0f;

#pragma unroll
        for (int kt = 0; kt < 8; kt++) {
            const int k = 8 * kt;
            int r0 = m0 + grp;
            uint32_t a0 = QsU[r0 * KS_STRIDE + k + qd];
            uint32_t a1 = QsU[(r0 + 8) * KS_STRIDE + k + qd];
            uint32_t a2 = QsU[r0 * KS_STRIDE + k + qd + 4];
            uint32_t a3 = QsU[(r0 + 8) * KS_STRIDE + k + qd + 4];
            uint32_t b[8][2];
#pragma unroll
            for (int jn = 0; jn < 8; jn++) {
                int n = ch * 64 + 8 * jn + grp;
                b[jn][0] = KsU[n * KS_STRIDE + k + qd];
                b[jn][1] = KsU[n * KS_STRIDE + k + qd + 4];
            }
#pragma unroll
            for (int jn = 0; jn < 8; jn++)
                mma_tf32(sacc[jn][0], sacc[jn][1], sacc[jn][2], sacc[jn][3],
                         a0, a1, a2, a3, b[jn][0], b[jn][1]);
        }

        // ---- online softmax (branchless, per-lane partial l) ----
#pragma unroll
        for (int r = 0; r < 2; r++) {
            float mx = -1e30f;
#pragma unroll
            for (int jn = 0; jn < 8; jn++) {
                mx = fmaxf(mx, sacc[jn][2 * r]);
                mx = fmaxf(mx, sacc[jn][2 * r + 1]);
            }
            mx = fmaxf(mx, __shfl_xor_sync(0xffffffffu, mx, 1));
            mx = fmaxf(mx, __shfl_xor_sync(0xffffffffu, mx, 2));
            float mnew = fmaxf(mrow[r], mx);
            float scale = __expf(mrow[r] - mnew);
            mrow[r] = mnew;
            float ps = 0.0f;
#pragma unroll
            for (int jn = 0; jn < 8; jn++) {
                float p0 = __expf(sacc[jn][2 * r] - mnew);
                float p1 = __expf(sacc[jn][2 * r + 1] - mnew);
                sacc[jn][2 * r] = p0;
                sacc[jn][2 * r + 1] = p1;
                ps += p0 + p1;
                oacc[jn][2 * r] *= scale;
                oacc[jn][2 * r + 1] *= scale;
            }
            lrow[r] = lrow[r] * scale + ps;
        }

        // ---- O += P V : gather P (C-frag -> A-frag) via quad shuffles ----
#pragma unroll
        for (int kt = 0; kt < 8; kt++) {
            float x0 = __shfl_sync(0xffffffffu, sacc[kt][0], src1);
            float x1 = __shfl_sync(0xffffffffu, sacc[kt][1], src1);
            float y0 = __shfl_sync(0xffffffffu, sacc[kt][2], src1);
            float y1 = __shfl_sync(0xffffffffu, sacc[kt][3], src1);
            float u0 = __shfl_sync(0xffffffffu, sacc[kt][0], src2);
            float u1 = __shfl_sync(0xffffffffu, sacc[kt][1], src2);
            float v0 = __shfl_sync(0xffffffffu, sacc[kt][2], src2);
            float v1 = __shfl_sync(0xffffffffu, sacc[kt][3], src2);
            uint32_t a0 = f2tf((qd & 1) ? x1 : x0);
            uint32_t a1 = f2tf((qd & 1) ? y1 : y0);
            uint32_t a2 = f2tf((qd & 1) ? u1 : u0);
            uint32_t a3 = f2tf((qd & 1) ? v1 : v0);
            const int k = ch * 64 + 8 * kt;
#pragma unroll
            for (int jn = 0; jn < 8; jn++) {
                int n = 8 * jn + grp;           // d-dimension
                uint32_t b0 = VtU[n * VT_STRIDE + k + qd];
                uint32_t b1 = VtU[n * VT_STRIDE + k + qd + 4];
                mma_tf32(oacc[jn][0], oacc[jn][1], oacc[jn][2], oacc[jn][3],
                         a0, a1, a2, a3, b0, b1);
            }
        }
    }

    // ---- finalize: reduce l over quad, normalize, store ----
    float inv[2];
#pragma unroll
    for (int r = 0; r < 2; r++) {
        float lr = lrow[r];
        lr += __shfl_xor_sync(0xffffffffu, lr, 1);
        lr += __shfl_xor_sync(0xffffffffu, lr, 2);
        inv[r] = 1.0f / lr;
    }
    float* o0 = g_O + base + (size_t)(m0 + grp) * DIM;
    float* o1 = g_O + base + (size_t)(m0 + grp + 8) * DIM;
#pragma unroll
    for (int jn = 0; jn < 8; jn++) {
        int col = 8 * jn + 2 * qd;
        *(float2*)&o0[col] = make_float2(oacc[jn][0] * inv[0], oacc[jn][1] * inv[0]);
        *(float2*)&o1[col] = make_float2(oacc[jn][2] * inv[1], oacc[jn][3] * inv[1]);
    }
}

// ---------------------------------------------------------------------------
// Kernel 3: output projection + bias (unchanged, passing).
// ---------------------------------------------------------------------------
__global__ __launch_bounds__(256)
void proj_tc_kernel(const float* __restrict__ Wo,
                    const float* __restrict__ bo,
                    float* __restrict__ out)
{
    extern __shared__ float smem[];

    const int nt = blockIdx.x;
    const int mt = blockIdx.y;

    const int tid  = threadIdx.x;
    const int wid  = tid >> 5;
    const int lane = tid & 31;
    const int wm   = (wid >> 2) * 64;
    const int wn   = (wid & 3) * 32;
    const int grp  = lane >> 2;
    const int qd   = lane & 3;

    const int arow = tid >> 3;
    const int akv  = tid & 7;

    float acc[4][4][4];
#pragma unroll
    for (int i = 0; i < 4; i++)
#pragma unroll
        for (int jn = 0; jn < 4; jn++)
#pragma unroll
            for (int c = 0; c < 4; c++)
                acc[i][jn][c] = 0.0f;

    float pa[16];
    float pb[16];

    auto loadA = [&](int k0) {
#pragma unroll
        for (int l = 0; l < 4; l++) {
            int row = arow + l * 32;
            float4 v = *(const float4*)(g_O +
                ((size_t)(mt * 128 + row)) * DIM + k0 + akv * 4);
            pa[l * 4 + 0] = v.x; pa[l * 4 + 1] = v.y;
            pa[l * 4 + 2] = v.z; pa[l * 4 + 3] = v.w;
        }
#pragma unroll
        for (int l = 0; l < 4; l++) {
            int n = arow + l * 32;
            float4 v = *(const float4*)(Wo +
                (size_t)(nt * 128 + n) * DIM + k0 + akv * 4);
            pb[l * 4 + 0] = v.x; pb[l * 4 + 1] = v.y;
            pb[l * 4 + 2] = v.z; pb[l * 4 + 3] = v.w;
        }
    };
    auto storeS = [&](float* Ab, float* Bb) {
#pragma unroll
        for (int l = 0; l < 4; l++) {
            int row = arow + l * 32;
            float* d = &Ab[row * SA + akv * 4];
            d[0] = to_tf32(pa[l * 4 + 0]); d[1] = to_tf32(pa[l * 4 + 1]);
            d[2] = to_tf32(pa[l * 4 + 2]); d[3] = to_tf32(pa[l * 4 + 3]);
        }
#pragma unroll
        for (int l = 0; l < 4; l++) {
            int n = arow + l * 32;
            float* d = &Bb[n * SB + akv * 4];
            d[0] = to_tf32(pb[l * 4 + 0]); d[1] = to_tf32(pb[l * 4 + 1]);
            d[2] = to_tf32(pb[l * 4 + 2]); d[3] = to_tf32(pb[l * 4 + 3]);
        }
    };

    loadA(0);
    storeS(smem, smem + 128 * SA);
    __syncthreads();

    int buf = 0;
    for (int kb = 0; kb < DIM / 32; kb++) {
        if (kb + 1 < DIM / 32) loadA((kb + 1) * 32);

        const float* Ab = smem + buf * BUF_FLOATS;
        const float* Bb = Ab + 128 * SA;
        const uint32_t* Asu = (const uint32_t*)Ab;
        const uint32_t* Bsu = (const uint32_t*)Bb;

#pragma unroll
        for (int kk = 0; kk < 4; kk++) {
            const int k = kk * 8;
            uint32_t a[4][4];
#pragma unroll
            for (int i = 0; i < 4; i++) {
                int r0 = wm + 16 * i + grp;
                a[i][0] = Asu[r0 * SA + k + qd];
                a[i][1] = Asu[(r0 + 8) * SA + k + qd];
                a[i][2] = Asu[r0 * SA + k + qd + 4];
                a[i][3] = Asu[(r0 + 8) * SA + k + qd + 4];
            }
            uint32_t b[4][2];
#pragma unroll
            for (int jn = 0; jn < 4; jn++) {
                int n = wn + 8 * jn + grp;
                b[jn][0] = Bsu[n * SB + k + qd];
                b[jn][1] = Bsu[n * SB + k + qd + 4];
            }
#pragma unroll
            for (int i = 0; i < 4; i++)
#pragma unroll
                for (int jn = 0; jn < 4; jn++)
                    mma_tf32(acc[i][jn][0], acc[i][jn][1], acc[i][jn][2], acc[i][jn][3],
                             a[i][0], a[i][1], a[i][2], a[i][3],
                             b[jn][0], b[jn][1]);
        }

        if (kb + 1 < DIM / 32) {
            float* Ab2 = smem + (buf ^ 1) * BUF_FLOATS;
            storeS(Ab2, Ab2 + 128 * SA);
        }
        __syncthreads();
        buf ^= 1;
    }

#pragma unroll
    for (int i = 0; i < 4; i++) {
        int r = mt * 128 + wm + 16 * i + grp;
        int b = r / (NJ * SEQT);
        int rem = r - b * (NJ * SEQT);
        int jj = rem >> 8;
        int t  = rem & (SEQT - 1);
        size_t base0 = (((size_t)(b * SEQT + t) * NJ) + jj) * DIM + nt * 128 + wn;
        size_t base1 = base0 + (size_t)8 * NJ * DIM;
#pragma unroll
        for (int jn = 0; jn < 4; jn++) {
            int col = 8 * jn + 2 * qd;
            float2 bb = *(const float2*)(bo + nt * 128 + wn + col);
            *(float2*)&out[base0 + col] = make_float2(acc[i][jn][0] + bb.x,
                                                      acc[i][jn][1] + bb.y);
            *(float2*)&out[base1 + col] = make_float2(acc[i][jn][2] + bb.x,
                                                      acc[i][jn][3] + bb.y);
        }
    }
}

// ---------------------------------------------------------------------------
extern "C" void kernel_launch(void* const* d_in, const int* in_sizes, int n_in,
                              void* d_out, int out_size)
{
    const float* x  = (const float*)d_in[0];
    const float* Wq = (const float*)d_in[1];
    const float* Wk = (const float*)d_in[2];
    const float* Wv = (const float*)d_in[3];
    const float* Wo = (const float*)d_in[4];
    const float* bo = (const float*)d_in[5];
    float* out = (float*)d_out;

    // 1) QKV projection
    cudaFuncSetAttribute(qkv_tc_kernel,
                         cudaFuncAttributeMaxDynamicSharedMemorySize, GEMM_SMEM);
    dim3 g1(DIM / 128, (BSZ * SEQT) / 128, 3 * NJ);   // (4, 16, 72)
    qkv_tc_kernel<<<g1, 256, GEMM_SMEM>>>(x, Wq, Wk, Wv);

    // 2) attention (tensor cores)
    cudaFuncSetAttribute(attn_tc_kernel,
                         cudaFuncAttributeMaxDynamicSharedMemorySize, ATT_SMEM);
    attn_tc_kernel<<<BSZ * NJ * NH, 512, ATT_SMEM>>>();

    // 3) output projection + bias
    cudaFuncSetAttribute(proj_tc_kernel,
                         cudaFuncAttributeMaxDynamicSharedMemorySize, GEMM_SMEM);
    dim3 g3(DIM / 128, (BSZ * SEQT * NJ) / 128);      // (4, 48)
    proj_tc_kernel<<<g3, 256, GEMM_SMEM>>>(Wo, bo, out);
}